// round 17
// baseline (speedup 1.0000x reference)
#include <cuda_runtime.h>
#include <cuda_bf16.h>
#include <cuda_fp16.h>
#include <cstdint>
#include <math.h>

#define BATCH 1024
#define IN_F  512
#define OUT_F 512
#define NC    35        // raw spline coefficients per (o,i)
#define ROWQ  41        // 16B slots per (i,opair) row: 40 segments + bw pair in slot 40
#define OT    16        // outputs per block
#define NPAIR 8         // output pairs per block (ol, ol+8)
#define ICH   32        // input features per block
#define NBI   (IN_F/ICH)
#define BT    512       // batches per block
#define C_BYTES  (NPAIR * ROWQ * 16)   // 5248
#define SCX_BYTES (BT * 8)             // 4096
#define TOT_BYTES (C_BYTES + SCX_BYTES)
#define RB    32        // table rows (io values) per prep_cub block
#define WST   37        // smem weight row stride (floats)
#define NSTG  3         // TMA pipeline stages

typedef unsigned long long ull;

// ---------------- scratch (device globals; no allocation) ----------------
// g_pk[i][pair][slot]: 16B = {h2(d0A,d0B), h2(d1A,d1B), h2(d2A,d2B), h2(d3A,d3B)}
// slot 40: {f32 bwA, f32 bwB, 0, 0}
__device__ uint4  g_pk[(size_t)IN_F * 256 * ROWQ];
__device__ float2 g_scx[IN_F * BATCH];   // [i][b] {f32 silu(x), bits: u16 m | f16 t}

// ---------------- P1: pair-slot build; coalesced reads AND 16B stores ----------------
__global__ __launch_bounds__(256) void prep_cub(const float* __restrict__ sw,
                                                const float* __restrict__ scaler,
                                                const int*   __restrict__ mask,
                                                const float* __restrict__ bwp) {
    __shared__ float s_w[RB * WST];      // raw weights, stride-37
    __shared__ float s_scal[RB];
    __shared__ int   s_msk[RB];
    __shared__ float s_bw[RB];

    const int io0 = blockIdx.x * RB;     // 32 consecutive io = i*512 + o
    const int tid = threadIdx.x;

    #pragma unroll
    for (int k = 0; k < 5; k++) {
        const int idx = tid + k * 256;               // RB*NC = 1120
        if (idx < RB * NC) {
            const int r = idx / NC;
            const int c = idx - r * NC;
            const int io = io0 + r;
            const int i  = io >> 9;
            const int o  = io & (OUT_F - 1);
            s_w[r * WST + c] = sw[(size_t)(o * IN_F + i) * NC + c];
        }
    }
    if (tid < RB) {
        const int io = io0 + tid;
        const int i  = io >> 9;
        const int o  = io & (OUT_F - 1);
        const int oi = o * IN_F + i;
        s_scal[tid] = scaler[oi];
        s_msk[tid]  = mask[oi];
        s_bw[tid]   = bwp[oi];
    }
    __syncthreads();

    auto coef = [&](int r, int m) -> float4 {
        const float s = s_scal[r];
        const float* wr = &s_w[r * WST];
        if (s_msk[r]) {
            const float s6 = s * (1.f / 6.f);
            const float ys = (wr[0]  + 4.f * wr[1]  + wr[2])  * s6;
            const float ye = (wr[32] + 4.f * wr[33] + wr[34]) * s6;
            const float a  = (ye - ys) * 0.5f;
            const float b0 = ys + a;
            return make_float4(fmaf(a, (float)(m - 20) * 0.0625f, b0),
                               a * 0.0625f, 0.f, 0.f);
        }
        if (m == 0 || m == 39) return make_float4(0.f, 0.f, 0.f, 0.f);
        const int cc = m - 4;
        const float v0 = (cc     >= 0) ? wr[cc]     * s : 0.f;
        const float v1 = (cc + 1 >= 0 && cc + 1 <= 34) ? wr[cc + 1] * s : 0.f;
        const float v2 = (cc + 2 >= 0 && cc + 2 <= 34) ? wr[cc + 2] * s : 0.f;
        const float v3 = (cc + 3 <= 34) ? wr[cc + 3] * s : 0.f;
        float4 v;
        v.x = (v0 + 4.f * v1 + v2) * (1.f / 6.f);
        v.y = (v2 - v0) * 0.5f;
        v.z = (v0 + v2) * 0.5f - v1;
        v.w = (3.f * (v1 - v2) + (v3 - v0)) * (1.f / 6.f);
        return v;
    };

    const int i  = io0 >> 9;
    const int ob = io0 & (OUT_F - 1);                // multiple of 32
    const size_t Pbase = ((size_t)i * 256 + (ob >> 4) * 8) * ROWQ;  // uint4 units

    #pragma unroll 1
    for (int idx = tid; idx < 16 * ROWQ; idx += 256) {
        const int pr = idx / ROWQ;
        const int m  = idx - pr * ROWQ;              // 0..40
        const int rA = ((pr >> 3) << 4) + (pr & 7);  // local o of output A
        const int rB = rA + 8;
        uint4 st;
        if (m == 40) {
            st.x = __float_as_uint(s_bw[rA]);
            st.y = __float_as_uint(s_bw[rB]);
            st.z = 0u; st.w = 0u;
        } else {
            const float4 vA = coef(rA, m);
            const float4 vB = coef(rB, m);
            // recenter at u = 0.5 (t = u - 0.5)
            const float d0A = vA.x + 0.5f * vA.y + 0.25f * vA.z + 0.125f * vA.w;
            const float d1A = vA.y + vA.z + 0.75f * vA.w;
            const float d2A = vA.z + 1.5f * vA.w;
            const float d0B = vB.x + 0.5f * vB.y + 0.25f * vB.z + 0.125f * vB.w;
            const float d1B = vB.y + vB.z + 0.75f * vB.w;
            const float d2B = vB.z + 1.5f * vB.w;
            const __half2 h0 = __floats2half2_rn(d0A, d0B);
            const __half2 h1 = __floats2half2_rn(d1A, d1B);
            const __half2 h2 = __floats2half2_rn(d2A, d2B);
            const __half2 h3 = __floats2half2_rn(vA.w, vB.w);
            st.x = *(const unsigned*)&h0;
            st.y = *(const unsigned*)&h1;
            st.z = *(const unsigned*)&h2;
            st.w = *(const unsigned*)&h3;
        }
        g_pk[Pbase + idx] = st;
    }
}

// ---------------- P2: {sx, packed(t fp16, m u16)} per (b,i) + zero out ----------------
__global__ void prep_bz(const float* __restrict__ x, float* __restrict__ out) {
    const int n = blockIdx.x * 256 + threadIdx.x;   // n = i*1024 + b
    const int i = n >> 10;
    const int b = n & 1023;
    const float xv = x[b * IN_F + i];
    const float sx = xv / (1.f + expf(-xv));
    const float sc = fmaf(xv, 16.f, 19.f);
    const float sgc = fminf(fmaxf(floorf(sc), -1.f), 38.f);
    const int   m  = (int)sgc + 1;                  // 0..39
    const float t  = sc - sgc - 0.5f;
    const unsigned pk = ((unsigned)m << 16)
                      | (unsigned)__half_as_ushort(__float2half_rn(t));
    g_scx[n] = make_float2(sx, __uint_as_float(pk));
    out[n]  = 0.f;                                  // BATCH*OUT_F == IN_F*BATCH
}

// ---------------- f32x2 packed helpers ----------------
__device__ __forceinline__ ull pack2(float a, float b) {
    ull r; asm("mov.b64 %0, {%1, %2};" : "=l"(r) : "f"(a), "f"(b)); return r;
}
__device__ __forceinline__ float2 unpack2(ull v) {
    float2 f; asm("mov.b64 {%0, %1}, %2;" : "=f"(f.x), "=f"(f.y) : "l"(v)); return f;
}
__device__ __forceinline__ ull fma2(ull a, ull b, ull c) {
    ull d; asm("fma.rn.f32x2 %0, %1, %2, %3;" : "=l"(d) : "l"(a), "l"(b), "l"(c)); return d;
}
__device__ __forceinline__ ull add2(ull a, ull b) {
    ull d; asm("add.rn.f32x2 %0, %1, %2;" : "=l"(d) : "l"(a), "l"(b)); return d;
}
__device__ __forceinline__ ull h2fx2(unsigned h) {   // f16x2 -> packed f32x2
    ull r;
    asm("{\n\t.reg .b16 lo, hi;\n\t.reg .f32 fl, fh;\n\t"
        "mov.b32 {lo, hi}, %1;\n\t"
        "cvt.f32.f16 fl, lo;\n\t"
        "cvt.f32.f16 fh, hi;\n\t"
        "mov.b64 %0, {fl, fh};\n\t}" : "=l"(r) : "r"(h));
    return r;
}

// ---------------- TMA bulk + mbarrier helpers ----------------
__device__ __forceinline__ unsigned smem_u32(const void* p) {
    return (unsigned)__cvta_generic_to_shared(p);
}
__device__ __forceinline__ void bulk_g2s(void* dst_smem, const void* src_gmem,
                                         unsigned bytes, unsigned mbar) {
    asm volatile(
        "cp.async.bulk.shared::cluster.global.mbarrier::complete_tx::bytes "
        "[%0], [%1], %2, [%3];\n"
        :: "r"(smem_u32(dst_smem)), "l"(src_gmem), "r"(bytes), "r"(mbar) : "memory");
}
#define MBAR_INIT(addr, cnt) \
    asm volatile("mbarrier.init.shared.b64 [%0], %1;" :: "r"(addr), "r"(cnt) : "memory")
#define MBAR_EXPECT_TX(addr, bytes) \
    asm volatile("mbarrier.arrive.expect_tx.shared.b64 _, [%0], %1;" \
                 :: "r"(addr), "r"(bytes) : "memory")
#define MBAR_WAIT(addr, parity) do {                                              \
    unsigned _m = (addr); unsigned _p = (parity); unsigned _done;                 \
    asm volatile("{\n\t.reg .pred p;\n\t"                                         \
        "mbarrier.try_wait.parity.acquire.cta.shared::cta.b64 p, [%1], %2;\n\t"   \
        "selp.b32 %0, 1, 0, p;\n\t}"                                              \
        : "=r"(_done) : "r"(_m), "r"(_p) : "memory");                             \
    if (!_done) {                                                                 \
        asm volatile("{\n\t.reg .pred P1;\n\t"                                    \
            "W1_%=:\n\t"                                                          \
            "mbarrier.try_wait.parity.acquire.cta.shared::cta.b64 P1, [%0], %1, 0x989680;\n\t" \
            "@P1 bra.uni W2_%=;\n\t"                                              \
            "bra.uni W1_%=;\n\t"                                                  \
            "W2_%=:\n\t}"                                                         \
            :: "r"(_m), "r"(_p) : "memory");                                      \
    }                                                                             \
} while (0)

// ---------------- main: 3-stage TMA ring; f32x2 dual-output Horner ----------------
__global__ __launch_bounds__(512, 2) void main_k(float* __restrict__ out) {
    __shared__ __align__(16) uint4  s_P[NSTG][NPAIR * ROWQ];
    __shared__ __align__(16) float2 s_scx[NSTG][BT];
    __shared__ __align__(8)  unsigned long long s_bar[NSTG];

    const int o0   = blockIdx.x * OT;
    const int boff = blockIdx.y * BT;
    const int i0   = blockIdx.z * ICH;
    const int tid  = threadIdx.x;
    const int w    = tid >> 5;
    const int lane = tid & 31;
    const int ol   = lane & 7;
    const int bg   = lane >> 3;
    const int tb   = w * 32 + bg * 8;        // thread's first b within block tile

    ull acc[8];
    #pragma unroll
    for (int j = 0; j < 8; j++) acc[j] = 0ull;   // bits of (0.f, 0.f)

    if (tid == 0) {
        #pragma unroll
        for (int s = 0; s < NSTG; s++) MBAR_INIT(smem_u32(&s_bar[s]), 1);
    }
    __syncthreads();

    auto issue = [&](int ii, int stg) {
        const int i = i0 + ii;
        const unsigned bar = smem_u32(&s_bar[stg]);
        MBAR_EXPECT_TX(bar, TOT_BYTES);
        bulk_g2s(&s_P[stg][0],
                 g_pk + ((size_t)i * 256 + blockIdx.x * NPAIR) * ROWQ, C_BYTES, bar);
        bulk_g2s(&s_scx[stg][0], g_scx + i * BATCH + boff, SCX_BYTES, bar);
    };

    if (tid == 0) { issue(0, 0); issue(1, 1); }   // prefetch distance 2

    int cs = 0, cp = 0;        // consumer stage / phase
    int iss = 2;               // next issue stage

    for (int ii = 0; ii < ICH; ii++) {
        MBAR_WAIT(smem_u32(&s_bar[cs]), cp);

        if (tid == 0 && ii + 2 < ICH) {
            issue(ii + 2, iss);
            if (++iss == NSTG) iss = 0;
        }

        const uint4* Pc = s_P[cs];
        const uint4 qb = Pc[ol * ROWQ + 40];
        const ull BW = pack2(__uint_as_float(qb.x), __uint_as_float(qb.y));

        const float4* scx4 = (const float4*)&s_scx[cs][tb];
        float4 p[4];
        #pragma unroll
        for (int q = 0; q < 4; q++) p[q] = scx4[q];   // (sx,pk,sx,pk)

        #pragma unroll
        for (int j = 0; j < 8; j++) {
            const float    sx = (j & 1) ? p[j >> 1].z : p[j >> 1].x;
            const unsigned pk = __float_as_uint((j & 1) ? p[j >> 1].w : p[j >> 1].y);
            const float t = __half2float(__ushort_as_half((unsigned short)pk));
            const int   m = pk >> 16;
            const uint4 q4 = Pc[ol * ROWQ + m];
            const ull D0 = h2fx2(q4.x);
            const ull D1 = h2fx2(q4.y);
            const ull D2 = h2fx2(q4.z);
            const ull D3 = h2fx2(q4.w);
            const ull T  = pack2(t, t);
            ull P2 = fma2(D3, T, D2);
            P2 = fma2(P2, T, D1);
            P2 = fma2(P2, T, D0);
            acc[j] = add2(acc[j], P2);
            acc[j] = fma2(BW, pack2(sx, sx), acc[j]);
        }

        __syncthreads();   // all threads done with stage cs -> it may be refilled

        if (++cs == NSTG) { cs = 0; cp ^= 1; }
    }

    #pragma unroll
    for (int j = 0; j < 8; j++) {
        const int b = boff + tb + j;
        const float2 f = unpack2(acc[j]);
        atomicAdd(&out[b * OUT_F + o0 + ol],     f.x);
        atomicAdd(&out[b * OUT_F + o0 + ol + 8], f.y);
    }
}

// ---------------- launch ----------------
extern "C" void kernel_launch(void* const* d_in, const int* in_sizes, int n_in,
                              void* d_out, int out_size) {
    const float* x      = (const float*)d_in[0];  // (1024, 512)
    const float* bw     = (const float*)d_in[1];  // (512, 512)
    const float* sw     = (const float*)d_in[2];  // (512, 512, 35)
    const float* scaler = (const float*)d_in[3];  // (512, 512)
    // d_in[4] = grid (uniform; derived analytically)
    const int*   mask   = (const int*)d_in[5];    // (512, 512)
    float* out = (float*)d_out;                   // (1024, 512)

    prep_cub<<<(IN_F * OUT_F) / RB, 256>>>(sw, scaler, mask, bw);
    prep_bz<<<(IN_F * BATCH) / 256, 256>>>(x, out);
    main_k<<<dim3(OUT_F / OT, BATCH / BT, NBI), 512>>>(out);
}